// round 9
// baseline (speedup 1.0000x reference)
#include <cuda_runtime.h>
#include <cstdint>
#include <cstddef>

// Problem constants (fixed by reference setup_inputs):
//   b=2, h=32, n=8192, d=128, e=128, BLOCK=64, num_block=128
//   query  [64, 8192, 128] f32   (b*h flattened)
//   output [64, 8192, 128] f32   (prefilled diag part; we add to it)
//   s      [32]            f32
//   kv     [64, 128, 128, 128] f32
//
// out[bh, blk*64+t, e] = output[...] + exp(-s[h]*(t+1)) * sum_d q[bh,blk*64+t,d]*kv[bh,blk,d,e]

#define QS 132              // padded row stride (floats) for Q in smem
#define KS 132              // padded row stride (floats) for KV in smem
#define SMEM_BYTES ((64 * QS + 128 * KS) * 4)

__device__ __forceinline__ uint32_t f2tf32(float f) {
    uint32_t u;
    asm("cvt.rna.tf32.f32 %0, %1;" : "=r"(u) : "f"(f));
    return u;
}

__global__ void __launch_bounds__(256, 2)
lightning_inter_kernel(const float* __restrict__ q,
                       const float* __restrict__ oin,
                       const float* __restrict__ s,
                       const float* __restrict__ kv,
                       float* __restrict__ out)
{
    extern __shared__ float smem[];
    float* sQ  = smem;               // [64][QS]
    float* sKV = smem + 64 * QS;     // [128][KS]

    const int blk  = blockIdx.x;     // 0..127  (which 64-row block)
    const int bh   = blockIdx.y;     // 0..63   (b*32 + h)
    const int tid  = threadIdx.x;
    const int lane = tid & 31;
    const int warp = tid >> 5;

    const size_t qbase  = ((size_t)bh * 8192 + (size_t)blk * 64) * 128;
    const size_t kvbase = ((size_t)bh * 128 + (size_t)blk) * (128 * 128);

    // ---- Stage Q tile: 64x128 f32 = 2048 float4 ----
    {
        const float4* qg = (const float4*)(q + qbase);
        #pragma unroll
        for (int i = 0; i < 8; i++) {
            int idx = tid + i * 256;         // 0..2047
            int row = idx >> 5;              // 0..63
            int c4  = idx & 31;              // 0..31
            float4 v = qg[idx];
            *(float4*)&sQ[row * QS + c4 * 4] = v;   // 528B row stride: 16B aligned
        }
    }
    // ---- Stage KV tile: 128x128 f32 = 4096 float4 ----
    {
        const float4* kg = (const float4*)(kv + kvbase);
        #pragma unroll
        for (int i = 0; i < 16; i++) {
            int idx = tid + i * 256;         // 0..4095
            int row = idx >> 5;              // 0..127 (d)
            int c4  = idx & 31;              // e/4
            float4 v = kg[idx];
            *(float4*)&sKV[row * KS + c4 * 4] = v;
        }
    }
    __syncthreads();

    // ---- Warp tiling: warp grid 2 (M) x 4 (N); warp tile 32x32 ----
    const int wm  = warp & 1;        // 0..1  -> rows [wm*32, +32)
    const int wn  = warp >> 1;       // 0..3  -> cols [wn*32, +32)
    const int gid = lane >> 2;       // 0..7
    const int tig = lane & 3;        // 0..3

    float acc[2][4][4];
    #pragma unroll
    for (int mi = 0; mi < 2; mi++)
        #pragma unroll
        for (int ni = 0; ni < 4; ni++)
            #pragma unroll
            for (int r = 0; r < 4; r++) acc[mi][ni][r] = 0.0f;

    // ---- Mainloop: 16 k-steps of K=8 (tf32 m16n8k8) ----
    #pragma unroll
    for (int ks = 0; ks < 16; ks++) {
        const int k0 = ks * 8;

        uint32_t af[2][4];
        #pragma unroll
        for (int mi = 0; mi < 2; mi++) {
            const int rb = wm * 32 + mi * 16 + gid;
            const float* base = &sQ[rb * QS + k0 + tig];
            af[mi][0] = f2tf32(base[0]);           // (row, col)
            af[mi][1] = f2tf32(base[8 * QS]);      // (row+8, col)
            af[mi][2] = f2tf32(base[4]);           // (row, col+4)
            af[mi][3] = f2tf32(base[8 * QS + 4]);  // (row+8, col+4)
        }

        uint32_t bf[4][2];
        #pragma unroll
        for (int ni = 0; ni < 4; ni++) {
            const int cb = wn * 32 + ni * 8 + gid; // n index
            const float* base = &sKV[(k0 + tig) * KS + cb];
            bf[ni][0] = f2tf32(base[0]);           // (k, n)
            bf[ni][1] = f2tf32(base[4 * KS]);      // (k+4, n)
        }

        #pragma unroll
        for (int mi = 0; mi < 2; mi++)
            #pragma unroll
            for (int ni = 0; ni < 4; ni++) {
                asm volatile(
                    "mma.sync.aligned.m16n8k8.row.col.f32.tf32.tf32.f32 "
                    "{%0,%1,%2,%3}, {%4,%5,%6,%7}, {%8,%9}, {%0,%1,%2,%3};\n"
                    : "+f"(acc[mi][ni][0]), "+f"(acc[mi][ni][1]),
                      "+f"(acc[mi][ni][2]), "+f"(acc[mi][ni][3])
                    : "r"(af[mi][0]), "r"(af[mi][1]), "r"(af[mi][2]), "r"(af[mi][3]),
                      "r"(bf[ni][0]), "r"(bf[ni][1]));
            }
    }

    // ---- Epilogue: out = oin + exp(-s*(t+1)) * acc ----
    const float  sv    = s[bh & 31];
    const size_t obase = (size_t)bh * 8192 + (size_t)blk * 64;

    #pragma unroll
    for (int mi = 0; mi < 2; mi++) {
        const int r0 = wm * 32 + mi * 16 + gid;          // local row for c0/c1
        const float d0 = __expf(-sv * (float)(r0 + 1));  // row r0
        const float d1 = __expf(-sv * (float)(r0 + 9));  // row r0+8
        #pragma unroll
        for (int ni = 0; ni < 4; ni++) {
            const int col = wn * 32 + ni * 8 + tig * 2;
            {
                const size_t off = (obase + r0) * 128 + col;
                float2 o = *(const float2*)&oin[off];
                o.x += d0 * acc[mi][ni][0];
                o.y += d0 * acc[mi][ni][1];
                *(float2*)&out[off] = o;
            }
            {
                const size_t off = (obase + r0 + 8) * 128 + col;
                float2 o = *(const float2*)&oin[off];
                o.x += d1 * acc[mi][ni][2];
                o.y += d1 * acc[mi][ni][3];
                *(float2*)&out[off] = o;
            }
        }
    }
}

extern "C" void kernel_launch(void* const* d_in, const int* in_sizes, int n_in,
                              void* d_out, int out_size)
{
    const float* q   = (const float*)d_in[0];
    const float* oin = (const float*)d_in[1];
    const float* s   = (const float*)d_in[2];
    const float* kv  = (const float*)d_in[3];
    float* out = (float*)d_out;

    cudaFuncSetAttribute(lightning_inter_kernel,
                         cudaFuncAttributeMaxDynamicSharedMemorySize, SMEM_BYTES);

    dim3 grid(128, 64);   // (num_block, b*h)
    lightning_inter_kernel<<<grid, 256, SMEM_BYTES>>>(q, oin, s, kv, out);
}

// round 10
// speedup vs baseline: 1.2931x; 1.2931x over previous
#include <cuda_runtime.h>
#include <cstdint>
#include <cstddef>

// Problem constants (fixed by reference setup_inputs):
//   b=2, h=32, n=8192, d=128, e=128, BLOCK=64, num_block=128
//   query  [64, 8192, 128] f32   (b*h flattened)
//   output [64, 8192, 128] f32   (prefilled diag part; we add to it)
//   s      [32]            f32
//   kv     [64, 128, 128, 128] f32
//
// out[bh, blk*64+t, e] = output[...] + exp(-s[h]*(t+1)) * sum_d q[...]*kv[...]
//
// R10: persistent CTAs (1 per SM), cp.async double-buffered tile pipeline,
//      oin register prefetch, B-fragment bank-conflict fix (KS=136).

#define QS 132               // Q smem row stride (floats): bank shift 4 -> A conflict-free
#define KS 136               // KV smem row stride (floats): bank shift 8 -> B conflict-free
#define QTILEF (64 * QS)     // floats per Q stage
#define KTILEF (128 * KS)    // floats per KV stage
#define STAGEF (QTILEF + KTILEF)
#define SMEM_BYTES (2 * STAGEF * 4)   // 206,848 B (double buffer)

#define NTILES 8192          // 64 bh * 128 blocks

__device__ __forceinline__ uint32_t f2tf32(float f) {
    uint32_t u;
    asm("cvt.rna.tf32.f32 %0, %1;" : "=r"(u) : "f"(f));
    return u;
}

__device__ __forceinline__ void cp16(uint32_t saddr, const float* g) {
    asm volatile("cp.async.cg.shared.global [%0], [%1], 16;\n"
                 :: "r"(saddr), "l"(g));
}

__global__ void __launch_bounds__(256, 1)
lightning_inter_kernel(const float* __restrict__ q,
                       const float* __restrict__ oin,
                       const float* __restrict__ s,
                       const float* __restrict__ kv,
                       float* __restrict__ out,
                       int grid)
{
    extern __shared__ float smem[];
    const uint32_t sbase = (uint32_t)__cvta_generic_to_shared(smem);

    const int tid  = threadIdx.x;
    const int lane = tid & 31;
    const int warp = tid >> 5;
    const int wm   = warp & 1;       // M-range: rows [wm*32, +32)
    const int wn   = warp >> 1;      // N-range: cols [wn*32, +32)
    const int gid  = lane >> 2;      // 0..7
    const int tig  = lane & 3;       // 0..3

    // ---- issue cp.async group for one tile into buffer `buf` ----
    auto stage = [&](int t, int buf) {
        const int bh = t >> 7, blk = t & 127;
        const float* qg = q  + ((size_t)bh * 8192 + (size_t)blk * 64) * 128;
        const float* kg = kv + ((size_t)bh * 128 + (size_t)blk) * 16384;
        const uint32_t sq = sbase + (uint32_t)buf * (STAGEF * 4);
        const uint32_t sk = sq + QTILEF * 4;
        #pragma unroll
        for (int i = 0; i < 8; i++) {             // Q: 2048 float4
            int idx = tid + i * 256;
            int row = idx >> 5, c4 = idx & 31;
            cp16(sq + (uint32_t)(row * QS + c4 * 4) * 4, qg + idx * 4);
        }
        #pragma unroll
        for (int i = 0; i < 16; i++) {            // KV: 4096 float4
            int idx = tid + i * 256;
            int row = idx >> 5, c4 = idx & 31;
            cp16(sk + (uint32_t)(row * KS + c4 * 4) * 4, kg + idx * 4);
        }
        asm volatile("cp.async.commit_group;\n");
    };

    int t = blockIdx.x;
    if (t < NTILES) stage(t, 0);

    int it = 0;
    for (; t < NTILES; t += grid, it++) {
        const int bh = t >> 7, blk = t & 127;
        const size_t obase = (size_t)bh * 8192 + (size_t)blk * 64;
        const float sv = s[bh & 31];

        // ---- prefetch oin for this tile into registers (hidden by mainloop) ----
        float2 orf[2][4][2];
        #pragma unroll
        for (int mi = 0; mi < 2; mi++) {
            const int r0 = wm * 32 + mi * 16 + gid;
            #pragma unroll
            for (int ni = 0; ni < 4; ni++) {
                const int col = wn * 32 + ni * 8 + tig * 2;
                orf[mi][ni][0] = *(const float2*)&oin[(obase + r0) * 128 + col];
                orf[mi][ni][1] = *(const float2*)&oin[(obase + r0 + 8) * 128 + col];
            }
        }

        // ---- prefetch next tile, wait for this one ----
        const int tn = t + grid;
        if (tn < NTILES) {
            stage(tn, (it + 1) & 1);
            asm volatile("cp.async.wait_group 1;\n");
        } else {
            asm volatile("cp.async.wait_group 0;\n");
        }
        __syncthreads();

        const float* sQ  = smem + (it & 1) * STAGEF;
        const float* sKV = sQ + QTILEF;

        float acc[2][4][4];
        #pragma unroll
        for (int mi = 0; mi < 2; mi++)
            #pragma unroll
            for (int ni = 0; ni < 4; ni++)
                #pragma unroll
                for (int r = 0; r < 4; r++) acc[mi][ni][r] = 0.0f;

        // ---- mainloop: 16 k-steps of m16n8k8 tf32 ----
        #pragma unroll
        for (int ks = 0; ks < 16; ks++) {
            const int k0 = ks * 8;

            uint32_t af[2][4];
            #pragma unroll
            for (int mi = 0; mi < 2; mi++) {
                const int rb = wm * 32 + mi * 16 + gid;
                const float* base = &sQ[rb * QS + k0 + tig];
                af[mi][0] = f2tf32(base[0]);
                af[mi][1] = f2tf32(base[8 * QS]);
                af[mi][2] = f2tf32(base[4]);
                af[mi][3] = f2tf32(base[8 * QS + 4]);
            }

            uint32_t bf[4][2];
            #pragma unroll
            for (int ni = 0; ni < 4; ni++) {
                const int cb = wn * 32 + ni * 8 + gid;
                const float* base = &sKV[(k0 + tig) * KS + cb];
                bf[ni][0] = f2tf32(base[0]);
                bf[ni][1] = f2tf32(base[4 * KS]);
            }

            #pragma unroll
            for (int mi = 0; mi < 2; mi++)
                #pragma unroll
                for (int ni = 0; ni < 4; ni++) {
                    asm volatile(
                        "mma.sync.aligned.m16n8k8.row.col.f32.tf32.tf32.f32 "
                        "{%0,%1,%2,%3}, {%4,%5,%6,%7}, {%8,%9}, {%0,%1,%2,%3};\n"
                        : "+f"(acc[mi][ni][0]), "+f"(acc[mi][ni][1]),
                          "+f"(acc[mi][ni][2]), "+f"(acc[mi][ni][3])
                        : "r"(af[mi][0]), "r"(af[mi][1]), "r"(af[mi][2]), "r"(af[mi][3]),
                          "r"(bf[ni][0]), "r"(bf[ni][1]));
                }
        }
        __syncthreads();   // smem reads done -> buffer may be overwritten next iter

        // ---- epilogue: out = oin + exp(-s*(t+1)) * acc (oin already in regs) ----
        #pragma unroll
        for (int mi = 0; mi < 2; mi++) {
            const int r0 = wm * 32 + mi * 16 + gid;
            const float d0 = __expf(-sv * (float)(r0 + 1));
            const float d1 = __expf(-sv * (float)(r0 + 9));
            #pragma unroll
            for (int ni = 0; ni < 4; ni++) {
                const int col = wn * 32 + ni * 8 + tig * 2;
                float2 o0 = orf[mi][ni][0];
                o0.x += d0 * acc[mi][ni][0];
                o0.y += d0 * acc[mi][ni][1];
                *(float2*)&out[(obase + r0) * 128 + col] = o0;
                float2 o1 = orf[mi][ni][1];
                o1.x += d1 * acc[mi][ni][2];
                o1.y += d1 * acc[mi][ni][3];
                *(float2*)&out[(obase + r0 + 8) * 128 + col] = o1;
            }
        }
    }
}

extern "C" void kernel_launch(void* const* d_in, const int* in_sizes, int n_in,
                              void* d_out, int out_size)
{
    const float* q   = (const float*)d_in[0];
    const float* oin = (const float*)d_in[1];
    const float* s   = (const float*)d_in[2];
    const float* kv  = (const float*)d_in[3];
    float* out = (float*)d_out;

    int dev = 0;
    cudaGetDevice(&dev);
    int nsm = 148;
    cudaDeviceGetAttribute(&nsm, cudaDevAttrMultiProcessorCount, dev);

    cudaFuncSetAttribute(lightning_inter_kernel,
                         cudaFuncAttributeMaxDynamicSharedMemorySize, SMEM_BYTES);

    lightning_inter_kernel<<<nsm, 256, SMEM_BYTES>>>(q, oin, s, kv, out, nsm);
}